// round 7
// baseline (speedup 1.0000x reference)
#include <cuda_runtime.h>
#include <cuda_bf16.h>
#include <cstdint>

// Problem constants (fixed-shape problem)
#define NNODES 50000
#define NEDGES 800000
#define NF     128
#define EF     32
#define HID    300
#define MSGD   128
#define NHID   128
#define NGRAPH 64

// Edge pipeline chunking: keeps total __device__ scratch < 2GB (host-side
// shadow vars of __device__ globals live in .bss; >2GB breaks GOTPCREL
// relocation against static cudart at link time).
#define ECHUNK 200000
#define NCHUNK (NEDGES / ECHUNK)

typedef unsigned long long u64;

// ---------------------------------------------------------------------------
// Scratch: __device__ globals (cudaMalloc is forbidden). Total ~830 MB.
// ---------------------------------------------------------------------------
__device__ float g_Pa[NNODES * HID];            // x @ W1[0:128] + b1   (dst proj)
__device__ float g_Pb[NNODES * HID];            // x @ W1[128:256]      (src proj)
__device__ float g_h1[(size_t)ECHUNK * HID];    // edge hidden 1 (chunk)
__device__ float g_h2[(size_t)ECHUNK * HID];    // edge hidden 2 (chunk)
__device__ float g_aggr[NNODES * MSGD];         // segment-summed messages
__device__ float g_u[NNODES * (NF + MSGD)];     // [x, aggr]
__device__ float g_n1[NNODES * HID];
__device__ float g_n2[NNODES * HID];
__device__ float g_hn[NNODES * NHID];           // per-node output
__device__ float g_pool[NGRAPH * NHID];
__device__ float g_cnt[NGRAPH];
__device__ int   g_src[NEDGES];
__device__ int   g_dst[NEDGES];
__device__ int   g_batch[NNODES];
__device__ int   g_e64;   // edge_index is int64?
__device__ int   g_b64;   // batch is int64?

// ---------------------------------------------------------------------------
// Packed fp32x2 FMA (Blackwell): two independent IEEE fp32 FMAs per issue.
// ptxas never emits FFMA2 from C++; explicit PTX is required.
// ---------------------------------------------------------------------------
__device__ __forceinline__ u64 ffma2(u64 a, u64 b, u64 c) {
    u64 d;
    asm("fma.rn.f32x2 %0, %1, %2, %3;" : "=l"(d) : "l"(a), "l"(b), "l"(c));
    return d;
}
__device__ __forceinline__ u64 pack2(float lo, float hi) {
    u64 d;
    asm("mov.b64 %0, {%1, %2};" : "=l"(d) : "f"(lo), "f"(hi));
    return d;
}

// ---------------------------------------------------------------------------
// dtype detection: int64 little-endian high words are 0 for values < 2^31.
// batch is SORTED (early values legitimately 0) -> sample odd words near END.
// edge_index values are uniform random -> sample first odd words.
// ---------------------------------------------------------------------------
__global__ void detect_k(const int* __restrict__ e, const int* __restrict__ b,
                         int nn) {
    __shared__ int se, sb;
    int t = threadIdx.x;
    if (t == 0) { se = 1; sb = 1; }
    __syncthreads();
    if (e[2 * t + 1] != 0) se = 0;
    int w = nn - 1 - 2 * t;
    if (b[w] != 0) sb = 0;
    __syncthreads();
    if (t == 0) { g_e64 = se; g_b64 = sb; }
}

__global__ void convert_k(const int* __restrict__ e, const int* __restrict__ b,
                          int ne, int nn) {
    int i = blockIdx.x * blockDim.x + threadIdx.x;
    int e64 = g_e64, b64 = g_b64;
    if (i < ne) {
        if (e64) { g_src[i] = e[2 * i];      g_dst[i] = e[2 * (ne + i)]; }
        else     { g_src[i] = e[i];          g_dst[i] = e[ne + i]; }
    }
    if (i < nn) g_batch[i] = b64 ? b[2 * i] : b[i];
}

__global__ void zero_k() {
    long i = blockIdx.x * (long)blockDim.x + threadIdx.x;
    long stride = gridDim.x * (long)blockDim.x;
    for (long j = i; j < (long)NNODES * MSGD; j += stride) g_aggr[j] = 0.0f;
    if (i < NGRAPH * NHID) g_pool[i] = 0.0f;
    if (i < NGRAPH) g_cnt[i] = 0.0f;
}

// ---------------------------------------------------------------------------
// Generic SGEMM with FFMA2 inner loop: C[M,N] = epilogue(A[M,K] @ B[K,N])
// BM=BN=128, BK=16, 256 threads, 8x8 per-thread tile, 2-stage smem pipeline.
// A tile stored in smem DUPLICATED as u64 {v,v} so the inner loop needs no
// register repacking; B fragments are adjacent column pairs (natural u64).
// MODE 0: C = (relu?)(acc + bias), store (float4)
// MODE 1: C = relu(acc + Pa[dst[row]] + Pb[src[row]]), store      (edge layer1)
// MODE 2: atomicAdd(C[dst[row]*ldc + col], acc + bias)            (edge layer3)
// ---------------------------------------------------------------------------
#define BM 128
#define BN 128
#define BK 16
#define TM 8
#define TN 8

template <int MODE>
__global__ void __launch_bounds__(256, 2)
sgemm_k(int M, int N, int K,
        const float* __restrict__ A, int lda,
        const float* __restrict__ B, int ldb,
        const float* __restrict__ bias,
        float* __restrict__ C, int ldc,
        int relu,
        const int* __restrict__ rdst, const int* __restrict__ rsrc,
        const float* __restrict__ Pa, const float* __restrict__ Pb, int ldp) {
    __shared__ u64   As[2][BK * BM];   // duplicated pairs: As[k][m] = {a,a}
    __shared__ float Bs[2][BK * BN];

    const int row0 = blockIdx.x * BM;
    const int col0 = blockIdx.y * BN;
    const int tid = threadIdx.x;
    const int tr = tid / (BN / TN);   // 0..15
    const int tc = tid % (BN / TN);   // 0..15

    const int aRow  = tid / (BK / 4); // 0..63
    const int aCol4 = tid % (BK / 4); // 0..3
    const int bRow  = tid / (BN / 4); // 0..7
    const int bCol4 = tid % (BN / 4); // 0..31

    u64 acc2[TM][TN / 2];
#pragma unroll
    for (int i = 0; i < TM; i++)
#pragma unroll
        for (int j = 0; j < TN / 2; j++) acc2[i][j] = 0ull;

    float4 va[2], vb[2];

    auto ldg = [&](int k0) {
#pragma unroll
        for (int r = 0; r < 2; r++) {
            int grow = row0 + aRow + r * 64;
            int gk = k0 + aCol4 * 4;
            va[r] = make_float4(0.f, 0.f, 0.f, 0.f);
            if (grow < M && gk < K)
                va[r] = *(const float4*)(A + (size_t)grow * lda + gk);
        }
#pragma unroll
        for (int r = 0; r < 2; r++) {
            int gk = k0 + bRow + r * 8;
            int gcol = col0 + bCol4 * 4;
            vb[r] = make_float4(0.f, 0.f, 0.f, 0.f);
            if (gk < K && gcol < N)
                vb[r] = *(const float4*)(B + (size_t)gk * ldb + gcol);
        }
    };

    auto sts = [&](int buf) {
#pragma unroll
        for (int r = 0; r < 2; r++) {
            As[buf][(aCol4 * 4 + 0) * BM + aRow + r * 64] = pack2(va[r].x, va[r].x);
            As[buf][(aCol4 * 4 + 1) * BM + aRow + r * 64] = pack2(va[r].y, va[r].y);
            As[buf][(aCol4 * 4 + 2) * BM + aRow + r * 64] = pack2(va[r].z, va[r].z);
            As[buf][(aCol4 * 4 + 3) * BM + aRow + r * 64] = pack2(va[r].w, va[r].w);
        }
#pragma unroll
        for (int r = 0; r < 2; r++)
            *(float4*)(&Bs[buf][(bRow + r * 8) * BN + bCol4 * 4]) = vb[r];
    };

    const int nst = (K + BK - 1) / BK;
    ldg(0);
    sts(0);
    __syncthreads();

    for (int s = 0; s < nst; s++) {
        const int buf = s & 1;
        if (s + 1 < nst) ldg((s + 1) * BK);   // prefetch next stage into regs
#pragma unroll
        for (int kk = 0; kk < BK; kk++) {
            u64 ra2[TM], rb2[TN / 2];
#pragma unroll
            for (int i = 0; i < TM; i += 2) {   // 16B-aligned pair loads
                ulonglong2 p = *(const ulonglong2*)&As[buf][kk * BM + tr * TM + i];
                ra2[i] = p.x; ra2[i + 1] = p.y;
            }
            {
                ulonglong2 p0 = *(const ulonglong2*)&Bs[buf][kk * BN + tc * TN];
                ulonglong2 p1 = *(const ulonglong2*)&Bs[buf][kk * BN + tc * TN + 4];
                rb2[0] = p0.x; rb2[1] = p0.y; rb2[2] = p1.x; rb2[3] = p1.y;
            }
#pragma unroll
            for (int i = 0; i < TM; i++)
#pragma unroll
                for (int j = 0; j < TN / 2; j++)
                    acc2[i][j] = ffma2(ra2[i], rb2[j], acc2[i][j]);
        }
        if (s + 1 < nst) {
            sts(buf ^ 1);
            __syncthreads();
        }
    }

    // epilogue (all cols are 4-aligned; N multiple of 4 -> float4-safe)
#pragma unroll
    for (int i = 0; i < TM; i++) {
        int row = row0 + tr * TM + i;
        if (row >= M) continue;
        const float* af = (const float*)&acc2[i][0];   // low word = even col
        int dn = 0, sn = 0;
        if (MODE == 1) { dn = rdst[row]; sn = rsrc[row]; }
        if (MODE == 2) { dn = rdst[row]; }
#pragma unroll
        for (int j = 0; j < TN; j += 4) {
            int col = col0 + tc * TN + j;
            if (col >= N) continue;
            float4 v = make_float4(af[j], af[j + 1], af[j + 2], af[j + 3]);
            if (bias) {
                float4 bb = *(const float4*)(bias + col);
                v.x += bb.x; v.y += bb.y; v.z += bb.z; v.w += bb.w;
            }
            if (MODE == 0) {
                if (relu) {
                    v.x = fmaxf(v.x, 0.f); v.y = fmaxf(v.y, 0.f);
                    v.z = fmaxf(v.z, 0.f); v.w = fmaxf(v.w, 0.f);
                }
                *(float4*)(C + (size_t)row * ldc + col) = v;
            } else if (MODE == 1) {
                float4 a4 = *(const float4*)(Pa + (size_t)dn * ldp + col);
                float4 b4 = *(const float4*)(Pb + (size_t)sn * ldp + col);
                v.x = fmaxf(v.x + a4.x + b4.x, 0.f);
                v.y = fmaxf(v.y + a4.y + b4.y, 0.f);
                v.z = fmaxf(v.z + a4.z + b4.z, 0.f);
                v.w = fmaxf(v.w + a4.w + b4.w, 0.f);
                *(float4*)(C + (size_t)row * ldc + col) = v;
            } else {
                float* p = C + (size_t)dn * ldc + col;
                atomicAdd(p + 0, v.x);
                atomicAdd(p + 1, v.y);
                atomicAdd(p + 2, v.z);
                atomicAdd(p + 3, v.w);
            }
        }
    }
}

// ---------------------------------------------------------------------------
// concat u = [x, aggr]
// ---------------------------------------------------------------------------
__global__ void concat_k(const float* __restrict__ x, int nn) {
    int idx = blockIdx.x * blockDim.x + threadIdx.x;
    int n = idx >> 8, c = idx & 255;
    if (n < nn)
        g_u[idx] = (c < NF) ? x[n * NF + c] : g_aggr[n * MSGD + (c - NF)];
}

// ---------------------------------------------------------------------------
// pool: segment-sum per graph + counts
// ---------------------------------------------------------------------------
__global__ void pool_k(const float* __restrict__ h, int nn) {
    int idx = blockIdx.x * blockDim.x + threadIdx.x;
    int n = idx >> 7, c = idx & 127;
    if (n < nn) {
        int b = g_batch[n];
        atomicAdd(&g_pool[b * NHID + c], h[idx]);
        if (c == 0) atomicAdd(&g_cnt[b], 1.0f);
    }
}

// ---------------------------------------------------------------------------
// global MLP: one block per graph, 128 threads. pooled = pool/max(cnt,1);
// out = mlp3(pooled)
// ---------------------------------------------------------------------------
__global__ void gmlp_k(const float* __restrict__ W1, const float* __restrict__ b1,
                       const float* __restrict__ W2, const float* __restrict__ b2,
                       const float* __restrict__ W3, const float* __restrict__ b3,
                       float* __restrict__ out) {
    int g = blockIdx.x, t = threadIdx.x;
    __shared__ float s_in[NHID], s_h[NHID];
    float c = fmaxf(g_cnt[g], 1.0f);
    s_in[t] = g_pool[g * NHID + t] / c;
    __syncthreads();
    float a = b1[t];
    for (int k = 0; k < NHID; k++) a += s_in[k] * W1[k * NHID + t];
    s_h[t] = fmaxf(a, 0.0f);
    __syncthreads();
    a = b2[t];
    for (int k = 0; k < NHID; k++) a += s_h[k] * W2[k * NHID + t];
    a = fmaxf(a, 0.0f);
    __syncthreads();
    s_in[t] = a * W3[t];           // W3 is [128,1]
    __syncthreads();
    for (int s = 64; s > 0; s >>= 1) {
        if (t < s) s_in[t] += s_in[t + s];
        __syncthreads();
    }
    if (t == 0) out[g] = s_in[0] + b3[0];
}

// ---------------------------------------------------------------------------
// launch
// ---------------------------------------------------------------------------
static dim3 gemm_grid(int M, int N) {
    return dim3((M + BM - 1) / BM, (N + BN - 1) / BN);
}

extern "C" void kernel_launch(void* const* d_in, const int* in_sizes, int n_in,
                              void* d_out, int out_size) {
    const float* x       = (const float*)d_in[0];
    const int*   eidx    = (const int*)d_in[1];   // int32 or int64, detected
    const float* eattr   = (const float*)d_in[2];
    const int*   batch   = (const int*)d_in[3];
    const float* msg_W1  = (const float*)d_in[4];
    const float* msg_b1  = (const float*)d_in[5];
    const float* msg_W2  = (const float*)d_in[6];
    const float* msg_b2  = (const float*)d_in[7];
    const float* msg_W3  = (const float*)d_in[8];
    const float* msg_b3  = (const float*)d_in[9];
    const float* node_W1 = (const float*)d_in[10];
    const float* node_b1 = (const float*)d_in[11];
    const float* node_W2 = (const float*)d_in[12];
    const float* node_b2 = (const float*)d_in[13];
    const float* node_W3 = (const float*)d_in[14];
    const float* node_b3 = (const float*)d_in[15];
    const float* glob_W1 = (const float*)d_in[16];
    const float* glob_b1 = (const float*)d_in[17];
    const float* glob_W2 = (const float*)d_in[18];
    const float* glob_b2 = (const float*)d_in[19];
    const float* glob_W3 = (const float*)d_in[20];
    const float* glob_b3 = (const float*)d_in[21];
    float* out = (float*)d_out;

    // scratch addresses
    float *pPa, *pPb, *ph1, *ph2, *pag, *pu, *pn1, *pn2, *phn;
    int *psrc, *pdst;
    cudaGetSymbolAddress((void**)&pPa, g_Pa);
    cudaGetSymbolAddress((void**)&pPb, g_Pb);
    cudaGetSymbolAddress((void**)&ph1, g_h1);
    cudaGetSymbolAddress((void**)&ph2, g_h2);
    cudaGetSymbolAddress((void**)&pag, g_aggr);
    cudaGetSymbolAddress((void**)&pu, g_u);
    cudaGetSymbolAddress((void**)&pn1, g_n1);
    cudaGetSymbolAddress((void**)&pn2, g_n2);
    cudaGetSymbolAddress((void**)&phn, g_hn);
    cudaGetSymbolAddress((void**)&psrc, g_src);
    cudaGetSymbolAddress((void**)&pdst, g_dst);

    const int NE = NEDGES, NN = NNODES;

    // 0. dtype detection + index normalization + zero accumulators
    detect_k<<<1, 64>>>(eidx, batch, NN);
    convert_k<<<(NE + 255) / 256, 256>>>(eidx, batch, NE, NN);
    zero_k<<<4096, 256>>>();

    // 1. node projections: Pa = x @ W1[0:128] + b1 ; Pb = x @ W1[128:256]
    sgemm_k<0><<<gemm_grid(NN, HID), 256>>>(NN, HID, NF, x, NF,
        msg_W1, HID, msg_b1, pPa, HID, 0, nullptr, nullptr, nullptr, nullptr, 0);
    sgemm_k<0><<<gemm_grid(NN, HID), 256>>>(NN, HID, NF, x, NF,
        msg_W1 + (size_t)NF * HID, HID, nullptr, pPb, HID, 0,
        nullptr, nullptr, nullptr, nullptr, 0);

    // 2-4. edge pipeline, chunked (keeps scratch < 2GB for the host linker)
    for (int c = 0; c < NCHUNK; c++) {
        const int e0 = c * ECHUNK;
        const int Mc = ECHUNK;

        // edge layer 1: h1 = relu(eattr @ W1c + Pa[dst] + Pb[src])
        sgemm_k<1><<<gemm_grid(Mc, HID), 256>>>(Mc, HID, EF,
            eattr + (size_t)e0 * EF, EF,
            msg_W1 + (size_t)(2 * NF) * HID, HID, nullptr, ph1, HID, 1,
            pdst + e0, psrc + e0, pPa, pPb, HID);

        // edge layer 2: h2 = relu(h1 @ W2 + b2)   (the big GEMM)
        sgemm_k<0><<<gemm_grid(Mc, HID), 256>>>(Mc, HID, HID, ph1, HID,
            msg_W2, HID, msg_b2, ph2, HID, 1,
            nullptr, nullptr, nullptr, nullptr, 0);

        // edge layer 3 + scatter: aggr[dst] += h2 @ W3 + b3
        sgemm_k<2><<<gemm_grid(Mc, MSGD), 256>>>(Mc, MSGD, HID, ph2, HID,
            msg_W3, MSGD, msg_b3, pag, MSGD, 0,
            pdst + e0, nullptr, nullptr, nullptr, 0);
    }

    // 5. node MLP on [x, aggr]
    concat_k<<<(NN * 256 + 255) / 256, 256>>>(x, NN);
    sgemm_k<0><<<gemm_grid(NN, HID), 256>>>(NN, HID, NF + MSGD, pu, NF + MSGD,
        node_W1, HID, node_b1, pn1, HID, 1, nullptr, nullptr, nullptr, nullptr, 0);
    sgemm_k<0><<<gemm_grid(NN, HID), 256>>>(NN, HID, HID, pn1, HID,
        node_W2, HID, node_b2, pn2, HID, 1, nullptr, nullptr, nullptr, nullptr, 0);
    sgemm_k<0><<<gemm_grid(NN, NHID), 256>>>(NN, NHID, HID, pn2, HID,
        node_W3, NHID, node_b3, phn, NHID, 0, nullptr, nullptr, nullptr, nullptr, 0);

    // 6. mean pool per graph + global MLP
    pool_k<<<(NN * NHID + 255) / 256, 256>>>(phn, NN);
    gmlp_k<<<NGRAPH, NHID>>>(glob_W1, glob_b1, glob_W2, glob_b2,
                             glob_W3, glob_b3, out);
}

// round 9
// speedup vs baseline: 1.2090x; 1.2090x over previous
#include <cuda_runtime.h>
#include <cuda_bf16.h>
#include <cstdint>

// Problem constants (fixed-shape problem)
#define NNODES 50000
#define NEDGES 800000
#define NF     128
#define EF     32
#define HID    300
#define MSGD   128
#define NHID   128
#define NGRAPH 64

// Edge pipeline chunking: keeps total __device__ scratch < 2GB (host-side
// shadow vars of __device__ globals live in .bss; >2GB breaks GOTPCREL
// relocation against static cudart at link time).
#define ECHUNK 200000
#define NCHUNK (NEDGES / ECHUNK)

typedef unsigned long long u64;

// ---------------------------------------------------------------------------
// Scratch: __device__ globals (cudaMalloc is forbidden). Total ~830 MB.
// ---------------------------------------------------------------------------
__device__ float g_Pa[NNODES * HID];            // x @ W1[0:128] + b1   (dst proj)
__device__ float g_Pb[NNODES * HID];            // x @ W1[128:256]      (src proj)
__device__ float g_h1[(size_t)ECHUNK * HID];    // edge hidden 1 (chunk)
__device__ float g_h2[(size_t)ECHUNK * HID];    // edge hidden 2 (chunk)
__device__ float g_aggr[NNODES * MSGD];         // segment-summed messages
__device__ float g_u[NNODES * (NF + MSGD)];     // [x, aggr]
__device__ float g_n1[NNODES * HID];
__device__ float g_n2[NNODES * HID];
__device__ float g_hn[NNODES * NHID];           // per-node output
__device__ float g_pool[NGRAPH * NHID];
__device__ float g_cnt[NGRAPH];
__device__ int   g_src[NEDGES];
__device__ int   g_dst[NEDGES];
__device__ int   g_batch[NNODES];
__device__ int   g_e64;   // edge_index is int64?
__device__ int   g_b64;   // batch is int64?

// ---------------------------------------------------------------------------
// Packed fp32x2 FMA (Blackwell): two independent IEEE fp32 FMAs per issue.
// ptxas never emits FFMA2 from C++; explicit PTX is required.
// ---------------------------------------------------------------------------
__device__ __forceinline__ u64 ffma2(u64 a, u64 b, u64 c) {
    u64 d;
    asm("fma.rn.f32x2 %0, %1, %2, %3;" : "=l"(d) : "l"(a), "l"(b), "l"(c));
    return d;
}
__device__ __forceinline__ u64 pack2(float lo, float hi) {
    u64 d;
    asm("mov.b64 %0, {%1, %2};" : "=l"(d) : "f"(lo), "f"(hi));
    return d;
}

// ---------------------------------------------------------------------------
// dtype detection: int64 little-endian high words are 0 for values < 2^31.
// batch is SORTED (early values legitimately 0) -> sample odd words near END.
// edge_index values are uniform random -> sample first odd words.
// ---------------------------------------------------------------------------
__global__ void detect_k(const int* __restrict__ e, const int* __restrict__ b,
                         int nn) {
    __shared__ int se, sb;
    int t = threadIdx.x;
    if (t == 0) { se = 1; sb = 1; }
    __syncthreads();
    if (e[2 * t + 1] != 0) se = 0;
    int w = nn - 1 - 2 * t;
    if (b[w] != 0) sb = 0;
    __syncthreads();
    if (t == 0) { g_e64 = se; g_b64 = sb; }
}

__global__ void convert_k(const int* __restrict__ e, const int* __restrict__ b,
                          int ne, int nn) {
    int i = blockIdx.x * blockDim.x + threadIdx.x;
    int e64 = g_e64, b64 = g_b64;
    if (i < ne) {
        if (e64) { g_src[i] = e[2 * i];      g_dst[i] = e[2 * (ne + i)]; }
        else     { g_src[i] = e[i];          g_dst[i] = e[ne + i]; }
    }
    if (i < nn) g_batch[i] = b64 ? b[2 * i] : b[i];
}

__global__ void zero_k() {
    long i = blockIdx.x * (long)blockDim.x + threadIdx.x;
    long stride = gridDim.x * (long)blockDim.x;
    for (long j = i; j < (long)NNODES * MSGD; j += stride) g_aggr[j] = 0.0f;
    if (i < NGRAPH * NHID) g_pool[i] = 0.0f;
    if (i < NGRAPH) g_cnt[i] = 0.0f;
}

// ---------------------------------------------------------------------------
// SGEMM with FFMA2, zero extra LDS traffic:
//   A fragments are NATURAL u64 pairs along M (As[k][m] is m-contiguous),
//   accumulators pair two M-rows; B is duplicated {b,b} in registers
//   (8 movs per kk, amortized over 32 FFMA2).
// BM=BN=128, BK=16, 256 threads, 8x8 per-thread tile, 2-stage smem pipeline.
// MODE 0: C = (relu?)(acc + bias), store (float4)
// MODE 1: C = relu(acc + Pa[dst[row]] + Pb[src[row]]), store      (edge layer1)
// MODE 2: atomicAdd(C[dst[row]*ldc + col], acc + bias)            (edge layer3)
// ---------------------------------------------------------------------------
#define BM 128
#define BN 128
#define BK 16
#define TM 8
#define TN 8

template <int MODE>
__global__ void __launch_bounds__(256, 2)
sgemm_k(int M, int N, int K,
        const float* __restrict__ A, int lda,
        const float* __restrict__ B, int ldb,
        const float* __restrict__ bias,
        float* __restrict__ C, int ldc,
        int relu,
        const int* __restrict__ rdst, const int* __restrict__ rsrc,
        const float* __restrict__ Pa, const float* __restrict__ Pb, int ldp) {
    __shared__ float As[2][BK * BM];   // transposed: As[k][m], m contiguous
    __shared__ float Bs[2][BK * BN];

    const int row0 = blockIdx.x * BM;
    const int col0 = blockIdx.y * BN;
    const int tid = threadIdx.x;
    const int tr = tid / (BN / TN);   // 0..15
    const int tc = tid % (BN / TN);   // 0..15

    const int aRow  = tid / (BK / 4); // 0..63
    const int aCol4 = tid % (BK / 4); // 0..3
    const int bRow  = tid / (BN / 4); // 0..7
    const int bCol4 = tid % (BN / 4); // 0..31

    // acc2[i2][j] = {C[2*i2][j], C[2*i2+1][j]}  (lo word = even M row)
    u64 acc2[TM / 2][TN];
#pragma unroll
    for (int i = 0; i < TM / 2; i++)
#pragma unroll
        for (int j = 0; j < TN; j++) acc2[i][j] = 0ull;

    float4 va[2], vb[2];

    auto ldg = [&](int k0) {
#pragma unroll
        for (int r = 0; r < 2; r++) {
            int grow = row0 + aRow + r * 64;
            int gk = k0 + aCol4 * 4;
            va[r] = make_float4(0.f, 0.f, 0.f, 0.f);
            if (grow < M && gk < K)
                va[r] = *(const float4*)(A + (size_t)grow * lda + gk);
        }
#pragma unroll
        for (int r = 0; r < 2; r++) {
            int gk = k0 + bRow + r * 8;
            int gcol = col0 + bCol4 * 4;
            vb[r] = make_float4(0.f, 0.f, 0.f, 0.f);
            if (gk < K && gcol < N)
                vb[r] = *(const float4*)(B + (size_t)gk * ldb + gcol);
        }
    };

    auto sts = [&](int buf) {
#pragma unroll
        for (int r = 0; r < 2; r++) {
            As[buf][(aCol4 * 4 + 0) * BM + aRow + r * 64] = va[r].x;
            As[buf][(aCol4 * 4 + 1) * BM + aRow + r * 64] = va[r].y;
            As[buf][(aCol4 * 4 + 2) * BM + aRow + r * 64] = va[r].z;
            As[buf][(aCol4 * 4 + 3) * BM + aRow + r * 64] = va[r].w;
        }
#pragma unroll
        for (int r = 0; r < 2; r++)
            *(float4*)(&Bs[buf][(bRow + r * 8) * BN + bCol4 * 4]) = vb[r];
    };

    const int nst = (K + BK - 1) / BK;
    ldg(0);
    sts(0);
    __syncthreads();

    for (int s = 0; s < nst; s++) {
        const int buf = s & 1;
        if (s + 1 < nst) ldg((s + 1) * BK);   // prefetch next stage into regs
#pragma unroll
        for (int kk = 0; kk < BK; kk++) {
            // A: natural M-pairs, 2x LDS.128 (32B)
            ulonglong2 pa0 = *(const ulonglong2*)&As[buf][kk * BM + tr * TM];
            ulonglong2 pa1 = *(const ulonglong2*)&As[buf][kk * BM + tr * TM + 4];
            u64 ra2[TM / 2] = {pa0.x, pa0.y, pa1.x, pa1.y};
            // B: 8 floats (32B), duplicated into u64 pairs in registers
            float4 b0 = *(const float4*)&Bs[buf][kk * BN + tc * TN];
            float4 b1 = *(const float4*)&Bs[buf][kk * BN + tc * TN + 4];
            u64 rb2[TN];
            rb2[0] = pack2(b0.x, b0.x); rb2[1] = pack2(b0.y, b0.y);
            rb2[2] = pack2(b0.z, b0.z); rb2[3] = pack2(b0.w, b0.w);
            rb2[4] = pack2(b1.x, b1.x); rb2[5] = pack2(b1.y, b1.y);
            rb2[6] = pack2(b1.z, b1.z); rb2[7] = pack2(b1.w, b1.w);
#pragma unroll
            for (int i = 0; i < TM / 2; i++)
#pragma unroll
                for (int j = 0; j < TN; j++)
                    acc2[i][j] = ffma2(ra2[i], rb2[j], acc2[i][j]);
        }
        if (s + 1 < nst) {
            sts(buf ^ 1);
            __syncthreads();
        }
    }

    // epilogue: row 2*i2+w = word w of acc2[i2][*]
#pragma unroll
    for (int i2 = 0; i2 < TM / 2; i2++) {
        float2 f[TN];
#pragma unroll
        for (int j = 0; j < TN; j++) f[j] = *(float2*)&acc2[i2][j];
#pragma unroll
        for (int w = 0; w < 2; w++) {
            int row = row0 + tr * TM + 2 * i2 + w;
            if (row >= M) continue;
            int dn = 0, sn = 0;
            if (MODE == 1) { dn = rdst[row]; sn = rsrc[row]; }
            if (MODE == 2) { dn = rdst[row]; }
#pragma unroll
            for (int j = 0; j < TN; j += 4) {
                int col = col0 + tc * TN + j;
                if (col >= N) continue;
                float4 v;
                if (w == 0) v = make_float4(f[j].x, f[j+1].x, f[j+2].x, f[j+3].x);
                else        v = make_float4(f[j].y, f[j+1].y, f[j+2].y, f[j+3].y);
                if (bias) {
                    float4 bb = *(const float4*)(bias + col);
                    v.x += bb.x; v.y += bb.y; v.z += bb.z; v.w += bb.w;
                }
                if (MODE == 0) {
                    if (relu) {
                        v.x = fmaxf(v.x, 0.f); v.y = fmaxf(v.y, 0.f);
                        v.z = fmaxf(v.z, 0.f); v.w = fmaxf(v.w, 0.f);
                    }
                    *(float4*)(C + (size_t)row * ldc + col) = v;
                } else if (MODE == 1) {
                    float4 a4 = *(const float4*)(Pa + (size_t)dn * ldp + col);
                    float4 b4 = *(const float4*)(Pb + (size_t)sn * ldp + col);
                    v.x = fmaxf(v.x + a4.x + b4.x, 0.f);
                    v.y = fmaxf(v.y + a4.y + b4.y, 0.f);
                    v.z = fmaxf(v.z + a4.z + b4.z, 0.f);
                    v.w = fmaxf(v.w + a4.w + b4.w, 0.f);
                    *(float4*)(C + (size_t)row * ldc + col) = v;
                } else {
                    float* p = C + (size_t)dn * ldc + col;
                    atomicAdd(p + 0, v.x);
                    atomicAdd(p + 1, v.y);
                    atomicAdd(p + 2, v.z);
                    atomicAdd(p + 3, v.w);
                }
            }
        }
    }
}

// ---------------------------------------------------------------------------
// concat u = [x, aggr]
// ---------------------------------------------------------------------------
__global__ void concat_k(const float* __restrict__ x, int nn) {
    int idx = blockIdx.x * blockDim.x + threadIdx.x;
    int n = idx >> 8, c = idx & 255;
    if (n < nn)
        g_u[idx] = (c < NF) ? x[n * NF + c] : g_aggr[n * MSGD + (c - NF)];
}

// ---------------------------------------------------------------------------
// pool: segment-sum per graph + counts
// ---------------------------------------------------------------------------
__global__ void pool_k(const float* __restrict__ h, int nn) {
    int idx = blockIdx.x * blockDim.x + threadIdx.x;
    int n = idx >> 7, c = idx & 127;
    if (n < nn) {
        int b = g_batch[n];
        atomicAdd(&g_pool[b * NHID + c], h[idx]);
        if (c == 0) atomicAdd(&g_cnt[b], 1.0f);
    }
}

// ---------------------------------------------------------------------------
// global MLP: one block per graph, 128 threads. pooled = pool/max(cnt,1);
// out = mlp3(pooled)
// ---------------------------------------------------------------------------
__global__ void gmlp_k(const float* __restrict__ W1, const float* __restrict__ b1,
                       const float* __restrict__ W2, const float* __restrict__ b2,
                       const float* __restrict__ W3, const float* __restrict__ b3,
                       float* __restrict__ out) {
    int g = blockIdx.x, t = threadIdx.x;
    __shared__ float s_in[NHID], s_h[NHID];
    float c = fmaxf(g_cnt[g], 1.0f);
    s_in[t] = g_pool[g * NHID + t] / c;
    __syncthreads();
    float a = b1[t];
    for (int k = 0; k < NHID; k++) a += s_in[k] * W1[k * NHID + t];
    s_h[t] = fmaxf(a, 0.0f);
    __syncthreads();
    a = b2[t];
    for (int k = 0; k < NHID; k++) a += s_h[k] * W2[k * NHID + t];
    a = fmaxf(a, 0.0f);
    __syncthreads();
    s_in[t] = a * W3[t];           // W3 is [128,1]
    __syncthreads();
    for (int s = 64; s > 0; s >>= 1) {
        if (t < s) s_in[t] += s_in[t + s];
        __syncthreads();
    }
    if (t == 0) out[g] = s_in[0] + b3[0];
}

// ---------------------------------------------------------------------------
// launch
// ---------------------------------------------------------------------------
static dim3 gemm_grid(int M, int N) {
    return dim3((M + BM - 1) / BM, (N + BN - 1) / BN);
}

extern "C" void kernel_launch(void* const* d_in, const int* in_sizes, int n_in,
                              void* d_out, int out_size) {
    const float* x       = (const float*)d_in[0];
    const int*   eidx    = (const int*)d_in[1];   // int32 or int64, detected
    const float* eattr   = (const float*)d_in[2];
    const int*   batch   = (const int*)d_in[3];
    const float* msg_W1  = (const float*)d_in[4];
    const float* msg_b1  = (const float*)d_in[5];
    const float* msg_W2  = (const float*)d_in[6];
    const float* msg_b2  = (const float*)d_in[7];
    const float* msg_W3  = (const float*)d_in[8];
    const float* msg_b3  = (const float*)d_in[9];
    const float* node_W1 = (const float*)d_in[10];
    const float* node_b1 = (const float*)d_in[11];
    const float* node_W2 = (const float*)d_in[12];
    const float* node_b2 = (const float*)d_in[13];
    const float* node_W3 = (const float*)d_in[14];
    const float* node_b3 = (const float*)d_in[15];
    const float* glob_W1 = (const float*)d_in[16];
    const float* glob_b1 = (const float*)d_in[17];
    const float* glob_W2 = (const float*)d_in[18];
    const float* glob_b2 = (const float*)d_in[19];
    const float* glob_W3 = (const float*)d_in[20];
    const float* glob_b3 = (const float*)d_in[21];
    float* out = (float*)d_out;

    // scratch addresses
    float *pPa, *pPb, *ph1, *ph2, *pag, *pu, *pn1, *pn2, *phn;
    int *psrc, *pdst;
    cudaGetSymbolAddress((void**)&pPa, g_Pa);
    cudaGetSymbolAddress((void**)&pPb, g_Pb);
    cudaGetSymbolAddress((void**)&ph1, g_h1);
    cudaGetSymbolAddress((void**)&ph2, g_h2);
    cudaGetSymbolAddress((void**)&pag, g_aggr);
    cudaGetSymbolAddress((void**)&pu, g_u);
    cudaGetSymbolAddress((void**)&pn1, g_n1);
    cudaGetSymbolAddress((void**)&pn2, g_n2);
    cudaGetSymbolAddress((void**)&phn, g_hn);
    cudaGetSymbolAddress((void**)&psrc, g_src);
    cudaGetSymbolAddress((void**)&pdst, g_dst);

    const int NE = NEDGES, NN = NNODES;

    // 0. dtype detection + index normalization + zero accumulators
    detect_k<<<1, 64>>>(eidx, batch, NN);
    convert_k<<<(NE + 255) / 256, 256>>>(eidx, batch, NE, NN);
    zero_k<<<4096, 256>>>();

    // 1. node projections: Pa = x @ W1[0:128] + b1 ; Pb = x @ W1[128:256]
    sgemm_k<0><<<gemm_grid(NN, HID), 256>>>(NN, HID, NF, x, NF,
        msg_W1, HID, msg_b1, pPa, HID, 0, nullptr, nullptr, nullptr, nullptr, 0);
    sgemm_k<0><<<gemm_grid(NN, HID), 256>>>(NN, HID, NF, x, NF,
        msg_W1 + (size_t)NF * HID, HID, nullptr, pPb, HID, 0,
        nullptr, nullptr, nullptr, nullptr, 0);

    // 2-4. edge pipeline, chunked (keeps scratch < 2GB for the host linker)
    for (int c = 0; c < NCHUNK; c++) {
        const int e0 = c * ECHUNK;
        const int Mc = ECHUNK;

        // edge layer 1: h1 = relu(eattr @ W1c + Pa[dst] + Pb[src])
        sgemm_k<1><<<gemm_grid(Mc, HID), 256>>>(Mc, HID, EF,
            eattr + (size_t)e0 * EF, EF,
            msg_W1 + (size_t)(2 * NF) * HID, HID, nullptr, ph1, HID, 1,
            pdst + e0, psrc + e0, pPa, pPb, HID);

        // edge layer 2: h2 = relu(h1 @ W2 + b2)   (the big GEMM)
        sgemm_k<0><<<gemm_grid(Mc, HID), 256>>>(Mc, HID, HID, ph1, HID,
            msg_W2, HID, msg_b2, ph2, HID, 1,
            nullptr, nullptr, nullptr, nullptr, 0);

        // edge layer 3 + scatter: aggr[dst] += h2 @ W3 + b3
        sgemm_k<2><<<gemm_grid(Mc, MSGD), 256>>>(Mc, MSGD, HID, ph2, HID,
            msg_W3, MSGD, msg_b3, pag, MSGD, 0,
            pdst + e0, nullptr, nullptr, nullptr, 0);
    }

    // 5. node MLP on [x, aggr]
    concat_k<<<(NN * 256 + 255) / 256, 256>>>(x, NN);
    sgemm_k<0><<<gemm_grid(NN, HID), 256>>>(NN, HID, NF + MSGD, pu, NF + MSGD,
        node_W1, HID, node_b1, pn1, HID, 1, nullptr, nullptr, nullptr, nullptr, 0);
    sgemm_k<0><<<gemm_grid(NN, HID), 256>>>(NN, HID, HID, pn1, HID,
        node_W2, HID, node_b2, pn2, HID, 1, nullptr, nullptr, nullptr, nullptr, 0);
    sgemm_k<0><<<gemm_grid(NN, NHID), 256>>>(NN, NHID, HID, pn2, HID,
        node_W3, NHID, node_b3, phn, NHID, 0, nullptr, nullptr, nullptr, nullptr, 0);

    // 6. mean pool per graph + global MLP
    pool_k<<<(NN * NHID + 255) / 256, 256>>>(phn, NN);
    gmlp_k<<<NGRAPH, NHID>>>(glob_W1, glob_b1, glob_W2, glob_b2,
                             glob_W3, glob_b3, out);
}

// round 11
// speedup vs baseline: 2.0495x; 1.6952x over previous
#include <cuda_runtime.h>
#include <cuda_bf16.h>
#include <cstdint>

#define NNODES 50000
#define NEDGES 800000
#define NF     128
#define EF     32
#define HID    300
#define MSGD   128
#define NHID   128
#define NGRAPH 64

#define ECHUNK 200000
#define NCHUNK (NEDGES / ECHUNK)

typedef unsigned long long u64;

// ---------------------------------------------------------------------------
// Scratch (__device__ globals; total < 2GB to keep host .bss GOTPCREL-safe)
// ---------------------------------------------------------------------------
__device__ float g_Pa[NNODES * HID];
__device__ float g_Pb[NNODES * HID];
__device__ float g_h1[(size_t)ECHUNK * HID];
__device__ float g_h2[(size_t)ECHUNK * HID];
__device__ float g_aggr[NNODES * MSGD];
__device__ float g_u[NNODES * (NF + MSGD)];
__device__ float g_n1[NNODES * HID];
__device__ float g_n2[NNODES * HID];
__device__ float g_hn[NNODES * NHID];
__device__ float g_pool[NGRAPH * NHID];
__device__ float g_cnt[NGRAPH];
__device__ int   g_src[NEDGES];
__device__ int   g_dst[NEDGES];
__device__ int   g_batch[NNODES];
__device__ int   g_e64;
__device__ int   g_b64;

// Split-transposed weights: Wt[n][kpad] bf16 hi/lo
__device__ __nv_bfloat16 g_wpaH[300*128], g_wpaL[300*128];
__device__ __nv_bfloat16 g_wpbH[300*128], g_wpbL[300*128];
__device__ __nv_bfloat16 g_w2H [300*320], g_w2L [300*320];
__device__ __nv_bfloat16 g_w3H [128*320], g_w3L [128*320];
__device__ __nv_bfloat16 g_n1H [300*256], g_n1L [300*256];
__device__ __nv_bfloat16 g_n2H [300*320], g_n2L [300*320];
__device__ __nv_bfloat16 g_n3H [128*320], g_n3L [128*320];

// ---------------------------------------------------------------------------
// PTX helpers (sm_80-compatible: ldmatrix + mma.sync — legal on sm_100 target)
// ---------------------------------------------------------------------------
__device__ __forceinline__ uint32_t smem_u32(const void* p) {
    uint32_t a;
    asm("{ .reg .u64 t; cvta.to.shared.u64 t, %1; cvt.u32.u64 %0, t; }"
        : "=r"(a) : "l"(p));
    return a;
}
__device__ __forceinline__ void ldm_x4(uint32_t* r, uint32_t addr) {
    asm volatile("ldmatrix.sync.aligned.m8n8.x4.shared.b16 {%0,%1,%2,%3}, [%4];"
        : "=r"(r[0]), "=r"(r[1]), "=r"(r[2]), "=r"(r[3]) : "r"(addr));
}
__device__ __forceinline__ void mma16816(float* c, const uint32_t* a,
                                         const uint32_t* b) {
    asm volatile(
        "mma.sync.aligned.m16n8k16.row.col.f32.bf16.bf16.f32 "
        "{%0,%1,%2,%3}, {%4,%5,%6,%7}, {%8,%9}, {%0,%1,%2,%3};"
        : "+f"(c[0]), "+f"(c[1]), "+f"(c[2]), "+f"(c[3])
        : "r"(a[0]), "r"(a[1]), "r"(a[2]), "r"(a[3]), "r"(b[0]), "r"(b[1]));
}

// ---------------------------------------------------------------------------
// small kernels
// ---------------------------------------------------------------------------
__global__ void detect_k(const int* __restrict__ e, const int* __restrict__ b, int nn) {
    __shared__ int se, sb;
    int t = threadIdx.x;
    if (t == 0) { se = 1; sb = 1; }
    __syncthreads();
    if (e[2 * t + 1] != 0) se = 0;
    int w = nn - 1 - 2 * t;
    if (b[w] != 0) sb = 0;
    __syncthreads();
    if (t == 0) { g_e64 = se; g_b64 = sb; }
}
__global__ void convert_k(const int* __restrict__ e, const int* __restrict__ b,
                          int ne, int nn) {
    int i = blockIdx.x * blockDim.x + threadIdx.x;
    int e64 = g_e64, b64 = g_b64;
    if (i < ne) {
        if (e64) { g_src[i] = e[2 * i]; g_dst[i] = e[2 * (ne + i)]; }
        else     { g_src[i] = e[i];     g_dst[i] = e[ne + i]; }
    }
    if (i < nn) g_batch[i] = b64 ? b[2 * i] : b[i];
}
__global__ void zero_k() {
    long i = blockIdx.x * (long)blockDim.x + threadIdx.x;
    long stride = gridDim.x * (long)blockDim.x;
    for (long j = i; j < (long)NNODES * MSGD; j += stride) g_aggr[j] = 0.0f;
    if (i < NGRAPH * NHID) g_pool[i] = 0.0f;
    if (i < NGRAPH) g_cnt[i] = 0.0f;
}
// W[K][N] row-major (ld=ldw) -> hi/lo [N][kpad] bf16, zero-padded in k
__global__ void wprep_k(const float* __restrict__ W, int K, int Nw, int ldw,
                        __nv_bfloat16* __restrict__ hi, __nv_bfloat16* __restrict__ lo,
                        int kpad) {
    int idx = blockIdx.x * blockDim.x + threadIdx.x;
    if (idx >= Nw * kpad) return;
    int n = idx / kpad, k = idx % kpad;
    float v = (k < K) ? W[(size_t)k * ldw + n] : 0.0f;
    __nv_bfloat16 h = __float2bfloat16(v);
    hi[idx] = h;
    lo[idx] = __float2bfloat16(v - __bfloat162float(h));
}

// ---------------------------------------------------------------------------
// Tensor GEMM via mma.sync bf16 split (3 products, fp32 accum).
// C[M,N] = epi(A[M,K]fp32 @ Wt^T), Wt pre-split [N][kpad] hi/lo bf16.
// CTA tile 128x64, BK=32, 256 thr (8 warps 4mx2n, warp 32x32 = 2x4 m16n8).
// Smem rows padded to 80B (40 bf16): stride 80 mod 128 hits distinct 16B
// banks for 8-row ldmatrix -> conflict-free without swizzle.
// MODE 0: C = (relu?)(acc+bias)   MODE 2: atomicAdd(C[rdst[row]], acc+bias)
// ---------------------------------------------------------------------------
#define RSB 80          // smem row stride bytes
#define OF_AH 0
#define OF_AL 10240     // 128*80
#define OF_BH 20480
#define OF_BL 25600     // +64*80
#define TBUF  30720
#define TSMEM (2*TBUF)  // 61440

template <int MODE>
__global__ void __launch_bounds__(256, 2)
tmma_k(int M, int N, int K,
       const float* __restrict__ A, int lda,
       const __nv_bfloat16* __restrict__ BH, const __nv_bfloat16* __restrict__ BL,
       int kpad,
       const float* __restrict__ bias,
       float* __restrict__ C, int ldc, int relu,
       const int* __restrict__ rdst) {
    extern __shared__ char sm[];
    const uint32_t smb = smem_u32(sm);
    const int tid = threadIdx.x;
    const int lane = tid & 31;
    const int wid = tid >> 5;
    const int wm = wid & 3, wn = wid >> 2;     // 4x2 warp grid
    const int col0 = blockIdx.x * 64;
    const int row0 = blockIdx.y * 128;

    float cc[2][4][4];
#pragma unroll
    for (int a = 0; a < 2; a++)
#pragma unroll
        for (int b = 0; b < 4; b++)
#pragma unroll
            for (int c = 0; c < 4; c++) cc[a][b][c] = 0.0f;

    // prefetch regs
    float4 va[4];            // 16 fp32 of A
    uint4 vbh, vbl;          // 8+8 bf16 of B

    const int rowA = tid >> 1, halfA = tid & 1;       // A: row, 16-elem half
    const int nB = tid >> 2, segB = tid & 3;          // B: n row, 16B segment

    auto ldgA = [&](int k0) {
        int grow = row0 + rowA;
        const float* p = A + (size_t)grow * lda + k0 + halfA * 16;
        if (grow < M && k0 + halfA * 16 + 16 <= K) {
            va[0] = ((const float4*)p)[0]; va[1] = ((const float4*)p)[1];
            va[2] = ((const float4*)p)[2]; va[3] = ((const float4*)p)[3];
        } else {
            float* vf = (float*)va;
#pragma unroll
            for (int j = 0; j < 16; j++) {
                int gk = k0 + halfA * 16 + j;
                vf[j] = (grow < M && gk < K) ? p[j] : 0.0f;
            }
        }
    };
    auto ldgB = [&](int k0) {
        if (col0 + nB < N) {
            vbh = *(const uint4*)(BH + (size_t)(col0 + nB) * kpad + k0 + segB * 8);
            vbl = *(const uint4*)(BL + (size_t)(col0 + nB) * kpad + k0 + segB * 8);
        } else {
            vbh = make_uint4(0, 0, 0, 0);
            vbl = make_uint4(0, 0, 0, 0);
        }
    };
    auto sts = [&](int buf) {
        // A: split fp32 -> hi/lo bf16
        uint32_t hw[8], lw[8];
        const float* vf = (const float*)va;
#pragma unroll
        for (int j = 0; j < 8; j++) {
            float v0 = vf[2 * j], v1 = vf[2 * j + 1];
            __nv_bfloat16 h0 = __float2bfloat16(v0), h1 = __float2bfloat16(v1);
            __nv_bfloat16 l0 = __float2bfloat16(v0 - __bfloat162float(h0));
            __nv_bfloat16 l1 = __float2bfloat16(v1 - __bfloat162float(h1));
            hw[j] = (uint32_t)__bfloat16_as_ushort(h0) |
                    ((uint32_t)__bfloat16_as_ushort(h1) << 16);
            lw[j] = (uint32_t)__bfloat16_as_ushort(l0) |
                    ((uint32_t)__bfloat16_as_ushort(l1) << 16);
        }
        char* ba = sm + buf + OF_AH + rowA * RSB + halfA * 32;
        *(uint4*)(ba +  0) = make_uint4(hw[0], hw[1], hw[2], hw[3]);
        *(uint4*)(ba + 16) = make_uint4(hw[4], hw[5], hw[6], hw[7]);
        char* bl_ = sm + buf + OF_AL + rowA * RSB + halfA * 32;
        *(uint4*)(bl_ +  0) = make_uint4(lw[0], lw[1], lw[2], lw[3]);
        *(uint4*)(bl_ + 16) = make_uint4(lw[4], lw[5], lw[6], lw[7]);
        *(uint4*)(sm + buf + OF_BH + nB * RSB + segB * 16) = vbh;
        *(uint4*)(sm + buf + OF_BL + nB * RSB + segB * 16) = vbl;
    };
    auto compute = [&](int buf) {
#pragma unroll
        for (int k16 = 0; k16 < 32; k16 += 16) {
            uint32_t ah[2][4], al[2][4], bh[4][2], bl2[4][2];
#pragma unroll
            for (int mt = 0; mt < 2; mt++) {
                uint32_t ad = smb + buf + OF_AH
                    + (uint32_t)(wm * 32 + mt * 16 + (lane & 15)) * RSB
                    + (uint32_t)(k16 + (lane >> 4) * 8) * 2;
                ldm_x4(ah[mt], ad);
                ldm_x4(al[mt], ad + (OF_AL - OF_AH));
            }
            {
                int g = lane >> 3, r = lane & 7;
#pragma unroll
                for (int np = 0; np < 2; np++) {
                    uint32_t bd = smb + buf + OF_BH
                        + (uint32_t)(wn * 32 + np * 16 + ((g >> 1) & 1) * 8 + r) * RSB
                        + (uint32_t)(k16 + (g & 1) * 8) * 2;
                    uint32_t t4[4];
                    ldm_x4(t4, bd);
                    bh[np * 2][0] = t4[0]; bh[np * 2][1] = t4[1];
                    bh[np * 2 + 1][0] = t4[2]; bh[np * 2 + 1][1] = t4[3];
                    ldm_x4(t4, bd + (OF_BL - OF_BH));
                    bl2[np * 2][0] = t4[0]; bl2[np * 2][1] = t4[1];
                    bl2[np * 2 + 1][0] = t4[2]; bl2[np * 2 + 1][1] = t4[3];
                }
            }
#pragma unroll
            for (int mt = 0; mt < 2; mt++)
#pragma unroll
                for (int nt = 0; nt < 4; nt++) {
                    mma16816(cc[mt][nt], ah[mt], bh[nt]);
                    mma16816(cc[mt][nt], ah[mt], bl2[nt]);
                    mma16816(cc[mt][nt], al[mt], bh[nt]);
                }
        }
    };

    const int nst = (K + 31) / 32;
    ldgA(0); ldgB(0);
    sts(0);
    __syncthreads();
    for (int s = 0; s < nst; s++) {
        const int buf = (s & 1) * TBUF;
        if (s + 1 < nst) { ldgA((s + 1) * 32); ldgB((s + 1) * 32); }
        compute(buf);
        if (s + 1 < nst) {
            sts(((s + 1) & 1) * TBUF);
            __syncthreads();
        }
    }

    // epilogue: c0,c1 -> (row, col..col+1); c2,c3 -> (row+8, ..)
#pragma unroll
    for (int mt = 0; mt < 2; mt++) {
#pragma unroll
        for (int h = 0; h < 2; h++) {
            int row = row0 + wm * 32 + mt * 16 + (lane >> 2) + h * 8;
            if (row >= M) continue;
            int dn = (MODE == 2) ? rdst[row] : 0;
#pragma unroll
            for (int nt = 0; nt < 4; nt++) {
                int col = col0 + wn * 32 + nt * 8 + (lane & 3) * 2;
                if (col >= N) continue;
                float v0 = cc[mt][nt][h * 2], v1 = cc[mt][nt][h * 2 + 1];
                if (bias) {
                    float2 bb = *(const float2*)(bias + col);
                    v0 += bb.x; v1 += bb.y;
                }
                if (MODE == 0) {
                    if (relu) { v0 = fmaxf(v0, 0.f); v1 = fmaxf(v1, 0.f); }
                    *(float2*)(C + (size_t)row * ldc + col) = make_float2(v0, v1);
                } else {
                    atomicAdd(C + (size_t)dn * ldc + col, v0);
                    atomicAdd(C + (size_t)dn * ldc + col + 1, v1);
                }
            }
        }
    }
}

// ---------------------------------------------------------------------------
// SIMT FFMA2 SGEMM — kept for MODE 1 (edge layer-1 gather epilogue, K=32)
// ---------------------------------------------------------------------------
#define BM 128
#define BN 128
#define BK 16
#define TM 8
#define TN 8
__device__ __forceinline__ u64 ffma2(u64 a, u64 b, u64 c) {
    u64 d;
    asm("fma.rn.f32x2 %0, %1, %2, %3;" : "=l"(d) : "l"(a), "l"(b), "l"(c));
    return d;
}
__device__ __forceinline__ u64 pack2(float lo, float hi) {
    u64 d;
    asm("mov.b64 %0, {%1, %2};" : "=l"(d) : "f"(lo), "f"(hi));
    return d;
}

template <int MODE>
__global__ void __launch_bounds__(256, 2)
sgemm_k(int M, int N, int K,
        const float* __restrict__ A, int lda,
        const float* __restrict__ B, int ldb,
        const float* __restrict__ bias,
        float* __restrict__ C, int ldc,
        int relu,
        const int* __restrict__ rdst, const int* __restrict__ rsrc,
        const float* __restrict__ Pa, const float* __restrict__ Pb, int ldp) {
    __shared__ float As[2][BK * BM];
    __shared__ float Bs[2][BK * BN];
    const int row0 = blockIdx.x * BM;
    const int col0 = blockIdx.y * BN;
    const int tid = threadIdx.x;
    const int tr = tid / (BN / TN);
    const int tc = tid % (BN / TN);
    const int aRow = tid / (BK / 4), aCol4 = tid % (BK / 4);
    const int bRow = tid / (BN / 4), bCol4 = tid % (BN / 4);

    u64 acc2[TM / 2][TN];
#pragma unroll
    for (int i = 0; i < TM / 2; i++)
#pragma unroll
        for (int j = 0; j < TN; j++) acc2[i][j] = 0ull;

    float4 va[2], vb[2];
    auto ldg = [&](int k0) {
#pragma unroll
        for (int r = 0; r < 2; r++) {
            int grow = row0 + aRow + r * 64, gk = k0 + aCol4 * 4;
            va[r] = make_float4(0.f, 0.f, 0.f, 0.f);
            if (grow < M && gk < K)
                va[r] = *(const float4*)(A + (size_t)grow * lda + gk);
        }
#pragma unroll
        for (int r = 0; r < 2; r++) {
            int gk = k0 + bRow + r * 8, gcol = col0 + bCol4 * 4;
            vb[r] = make_float4(0.f, 0.f, 0.f, 0.f);
            if (gk < K && gcol < N)
                vb[r] = *(const float4*)(B + (size_t)gk * ldb + gcol);
        }
    };
    auto sts = [&](int buf) {
#pragma unroll
        for (int r = 0; r < 2; r++) {
            As[buf][(aCol4 * 4 + 0) * BM + aRow + r * 64] = va[r].x;
            As[buf][(aCol4 * 4 + 1) * BM + aRow + r * 64] = va[r].y;
            As[buf][(aCol4 * 4 + 2) * BM + aRow + r * 64] = va[r].z;
            As[buf][(aCol4 * 4 + 3) * BM + aRow + r * 64] = va[r].w;
        }
#pragma unroll
        for (int r = 0; r < 2; r++)
            *(float4*)(&Bs[buf][(bRow + r * 8) * BN + bCol4 * 4]) = vb[r];
    };

    const int nst = (K + BK - 1) / BK;
    ldg(0); sts(0);
    __syncthreads();
    for (int s = 0; s < nst; s++) {
        const int buf = s & 1;
        if (s + 1 < nst) ldg((s + 1) * BK);
#pragma unroll
        for (int kk = 0; kk < BK; kk++) {
            ulonglong2 pa0 = *(const ulonglong2*)&As[buf][kk * BM + tr * TM];
            ulonglong2 pa1 = *(const ulonglong2*)&As[buf][kk * BM + tr * TM + 4];
            u64 ra2[TM / 2] = {pa0.x, pa0.y, pa1.x, pa1.y};
            float4 b0 = *(const float4*)&Bs[buf][kk * BN + tc * TN];
            float4 b1 = *(const float4*)&Bs[buf][kk * BN + tc * TN + 4];
            u64 rb2[TN];
            rb2[0] = pack2(b0.x, b0.x); rb2[1] = pack2(b0.y, b0.y);
            rb2[2] = pack2(b0.z, b0.z); rb2[3] = pack2(b0.w, b0.w);
            rb2[4] = pack2(b1.x, b1.x); rb2[5] = pack2(b1.y, b1.y);
            rb2[6] = pack2(b1.z, b1.z); rb2[7] = pack2(b1.w, b1.w);
#pragma unroll
            for (int i = 0; i < TM / 2; i++)
#pragma unroll
                for (int j = 0; j < TN; j++)
                    acc2[i][j] = ffma2(ra2[i], rb2[j], acc2[i][j]);
        }
        if (s + 1 < nst) { sts(buf ^ 1); __syncthreads(); }
    }

#pragma unroll
    for (int i2 = 0; i2 < TM / 2; i2++) {
        float2 f[TN];
#pragma unroll
        for (int j = 0; j < TN; j++) f[j] = *(float2*)&acc2[i2][j];
#pragma unroll
        for (int w = 0; w < 2; w++) {
            int row = row0 + tr * TM + 2 * i2 + w;
            if (row >= M) continue;
            int dn = 0, sn = 0;
            if (MODE == 1) { dn = rdst[row]; sn = rsrc[row]; }
            if (MODE == 2) { dn = rdst[row]; }
#pragma unroll
            for (int j = 0; j < TN; j += 4) {
                int col = col0 + tc * TN + j;
                if (col >= N) continue;
                float4 v;
                if (w == 0) v = make_float4(f[j].x, f[j+1].x, f[j+2].x, f[j+3].x);
                else        v = make_float4(f[j].y, f[j+1].y, f[j+2].y, f[j+3].y);
                if (bias) {
                    float4 bb = *(const float4*)(bias + col);
                    v.x += bb.x; v.y += bb.y; v.z += bb.z; v.w += bb.w;
                }
                if (MODE == 0) {
                    if (relu) {
                        v.x = fmaxf(v.x, 0.f); v.y = fmaxf(v.y, 0.f);
                        v.z = fmaxf(v.z, 0.f); v.w = fmaxf(v.w, 0.f);
                    }
                    *(float4*)(C + (size_t)row * ldc + col) = v;
                } else if (MODE == 1) {
                    float4 a4 = *(const float4*)(Pa + (size_t)dn * ldp + col);
                    float4 b4 = *(const float4*)(Pb + (size_t)sn * ldp + col);
                    v.x = fmaxf(v.x + a4.x + b4.x, 0.f);
                    v.y = fmaxf(v.y + a4.y + b4.y, 0.f);
                    v.z = fmaxf(v.z + a4.z + b4.z, 0.f);
                    v.w = fmaxf(v.w + a4.w + b4.w, 0.f);
                    *(float4*)(C + (size_t)row * ldc + col) = v;
                } else {
                    float* p = C + (size_t)dn * ldc + col;
                    atomicAdd(p + 0, v.x); atomicAdd(p + 1, v.y);
                    atomicAdd(p + 2, v.z); atomicAdd(p + 3, v.w);
                }
            }
        }
    }
}

__global__ void concat_k(const float* __restrict__ x, int nn) {
    int idx = blockIdx.x * blockDim.x + threadIdx.x;
    int n = idx >> 8, c = idx & 255;
    if (n < nn)
        g_u[idx] = (c < NF) ? x[n * NF + c] : g_aggr[n * MSGD + (c - NF)];
}
__global__ void pool_k(const float* __restrict__ h, int nn) {
    int idx = blockIdx.x * blockDim.x + threadIdx.x;
    int n = idx >> 7, c = idx & 127;
    if (n < nn) {
        int b = g_batch[n];
        atomicAdd(&g_pool[b * NHID + c], h[idx]);
        if (c == 0) atomicAdd(&g_cnt[b], 1.0f);
    }
}
__global__ void gmlp_k(const float* __restrict__ W1, const float* __restrict__ b1,
                       const float* __restrict__ W2, const float* __restrict__ b2,
                       const float* __restrict__ W3, const float* __restrict__ b3,
                       float* __restrict__ out) {
    int g = blockIdx.x, t = threadIdx.x;
    __shared__ float s_in[NHID], s_h[NHID];
    float c = fmaxf(g_cnt[g], 1.0f);
    s_in[t] = g_pool[g * NHID + t] / c;
    __syncthreads();
    float a = b1[t];
    for (int k = 0; k < NHID; k++) a += s_in[k] * W1[k * NHID + t];
    s_h[t] = fmaxf(a, 0.0f);
    __syncthreads();
    a = b2[t];
    for (int k = 0; k < NHID; k++) a += s_h[k] * W2[k * NHID + t];
    a = fmaxf(a, 0.0f);
    __syncthreads();
    s_in[t] = a * W3[t];
    __syncthreads();
    for (int s = 64; s > 0; s >>= 1) {
        if (t < s) s_in[t] += s_in[t + s];
        __syncthreads();
    }
    if (t == 0) out[g] = s_in[0] + b3[0];
}

// ---------------------------------------------------------------------------
// launch
// ---------------------------------------------------------------------------
extern "C" void kernel_launch(void* const* d_in, const int* in_sizes, int n_in,
                              void* d_out, int out_size) {
    const float* x       = (const float*)d_in[0];
    const int*   eidx    = (const int*)d_in[1];
    const float* eattr   = (const float*)d_in[2];
    const int*   batch   = (const int*)d_in[3];
    const float* msg_W1  = (const float*)d_in[4];
    const float* msg_b1  = (const float*)d_in[5];
    const float* msg_W2  = (const float*)d_in[6];
    const float* msg_b2  = (const float*)d_in[7];
    const float* msg_W3  = (const float*)d_in[8];
    const float* msg_b3  = (const float*)d_in[9];
    const float* node_W1 = (const float*)d_in[10];
    const float* node_b1 = (const float*)d_in[11];
    const float* node_W2 = (const float*)d_in[12];
    const float* node_b2 = (const float*)d_in[13];
    const float* node_W3 = (const float*)d_in[14];
    const float* node_b3 = (const float*)d_in[15];
    const float* glob_W1 = (const float*)d_in[16];
    const float* glob_b1 = (const float*)d_in[17];
    const float* glob_W2 = (const float*)d_in[18];
    const float* glob_b2 = (const float*)d_in[19];
    const float* glob_W3 = (const float*)d_in[20];
    const float* glob_b3 = (const float*)d_in[21];
    float* out = (float*)d_out;

    float *pPa, *pPb, *ph1, *ph2, *pag, *pu, *pn1, *pn2, *phn;
    int *psrc, *pdst;
    __nv_bfloat16 *paH,*paL,*pbH,*pbL,*w2H,*w2L,*w3H,*w3L,*n1H,*n1L,*n2H,*n2L,*n3H,*n3L;
    cudaGetSymbolAddress((void**)&pPa, g_Pa);
    cudaGetSymbolAddress((void**)&pPb, g_Pb);
    cudaGetSymbolAddress((void**)&ph1, g_h1);
    cudaGetSymbolAddress((void**)&ph2, g_h2);
    cudaGetSymbolAddress((void**)&pag, g_aggr);
    cudaGetSymbolAddress((void**)&pu, g_u);
    cudaGetSymbolAddress((void**)&pn1, g_n1);
    cudaGetSymbolAddress((void**)&pn2, g_n2);
    cudaGetSymbolAddress((void**)&phn, g_hn);
    cudaGetSymbolAddress((void**)&psrc, g_src);
    cudaGetSymbolAddress((void**)&pdst, g_dst);
    cudaGetSymbolAddress((void**)&paH, g_wpaH); cudaGetSymbolAddress((void**)&paL, g_wpaL);
    cudaGetSymbolAddress((void**)&pbH, g_wpbH); cudaGetSymbolAddress((void**)&pbL, g_wpbL);
    cudaGetSymbolAddress((void**)&w2H, g_w2H);  cudaGetSymbolAddress((void**)&w2L, g_w2L);
    cudaGetSymbolAddress((void**)&w3H, g_w3H);  cudaGetSymbolAddress((void**)&w3L, g_w3L);
    cudaGetSymbolAddress((void**)&n1H, g_n1H);  cudaGetSymbolAddress((void**)&n1L, g_n1L);
    cudaGetSymbolAddress((void**)&n2H, g_n2H);  cudaGetSymbolAddress((void**)&n2L, g_n2L);
    cudaGetSymbolAddress((void**)&n3H, g_n3H);  cudaGetSymbolAddress((void**)&n3L, g_n3L);

    cudaFuncSetAttribute(tmma_k<0>, cudaFuncAttributeMaxDynamicSharedMemorySize, TSMEM);
    cudaFuncSetAttribute(tmma_k<2>, cudaFuncAttributeMaxDynamicSharedMemorySize, TSMEM);

    const int NE = NEDGES, NN = NNODES;

    detect_k<<<1, 64>>>(eidx, batch, NN);
    convert_k<<<(NE + 255) / 256, 256>>>(eidx, batch, NE, NN);
    zero_k<<<4096, 256>>>();

    // weight split+transpose (kpad multiple of 32)
    wprep_k<<<(300*128 + 255)/256, 256>>>(msg_W1,           128, 300, 300, paH, paL, 128);
    wprep_k<<<(300*128 + 255)/256, 256>>>(msg_W1 + 128*300, 128, 300, 300, pbH, pbL, 128);
    wprep_k<<<(300*320 + 255)/256, 256>>>(msg_W2,           300, 300, 300, w2H, w2L, 320);
    wprep_k<<<(128*320 + 255)/256, 256>>>(msg_W3,           300, 128, 128, w3H, w3L, 320);
    wprep_k<<<(300*256 + 255)/256, 256>>>(node_W1,          256, 300, 300, n1H, n1L, 256);
    wprep_k<<<(300*320 + 255)/256, 256>>>(node_W2,          300, 300, 300, n2H, n2L, 320);
    wprep_k<<<(128*320 + 255)/256, 256>>>(node_W3,          300, 128, 128, n3H, n3L, 320);

    const int MT_N = (NN + 127) / 128;       // 391
    const int MT_E = (ECHUNK + 127) / 128;   // 1563

    // node projections (tensor): Pa = x@W1a + b1 ; Pb = x@W1b
    tmma_k<0><<<dim3(5, MT_N), 256, TSMEM>>>(NN, HID, NF, x, NF,
        paH, paL, 128, msg_b1, pPa, HID, 0, nullptr);
    tmma_k<0><<<dim3(5, MT_N), 256, TSMEM>>>(NN, HID, NF, x, NF,
        pbH, pbL, 128, nullptr, pPb, HID, 0, nullptr);

    // edge pipeline, chunked
    for (int c = 0; c < NCHUNK; c++) {
        const int e0 = c * ECHUNK;
        const int Mc = ECHUNK;
        // L1 (SIMT FFMA2, gather epilogue): h1 = relu(eattr@W1c + Pa[dst] + Pb[src])
        sgemm_k<1><<<dim3((Mc + BM - 1)/BM, (HID + BN - 1)/BN), 256>>>(Mc, HID, EF,
            eattr + (size_t)e0 * EF, EF,
            msg_W1 + (size_t)(2 * NF) * HID, HID, nullptr, ph1, HID, 1,
            pdst + e0, psrc + e0, pPa, pPb, HID);
        // L2 (tensor): h2 = relu(h1@W2 + b2)
        tmma_k<0><<<dim3(5, MT_E), 256, TSMEM>>>(Mc, HID, HID,
            ph1, HID, w2H, w2L, 320, msg_b2, ph2, HID, 1, nullptr);
        // L3 (tensor + scatter): aggr[dst] += h2@W3 + b3
        tmma_k<2><<<dim3(2, MT_E), 256, TSMEM>>>(Mc, MSGD, HID,
            ph2, HID, w3H, w3L, 320, msg_b3, pag, MSGD, 0, pdst + e0);
    }

    // node MLP (tensor)
    concat_k<<<(NN * 256 + 255) / 256, 256>>>(x, NN);
    tmma_k<0><<<dim3(5, MT_N), 256, TSMEM>>>(NN, HID, NF + MSGD, pu, NF + MSGD,
        n1H, n1L, 256, node_b1, pn1, HID, 1, nullptr);
    tmma_k<0><<<dim3(5, MT_N), 256, TSMEM>>>(NN, HID, HID, pn1, HID,
        n2H, n2L, 320, node_b2, pn2, HID, 1, nullptr);
    tmma_k<0><<<dim3(2, MT_N), 256, TSMEM>>>(NN, NHID, HID, pn2, HID,
        n3H, n3L, 320, node_b3, phn, NHID, 0, nullptr);

    // pool + global MLP
    pool_k<<<(NN * NHID + 255) / 256, 256>>>(phn, NN);
    gmlp_k<<<NGRAPH, NHID>>>(glob_W1, glob_b1, glob_W2, glob_b2,
                             glob_W3, glob_b3, out);
}